// round 14
// baseline (speedup 1.0000x reference)
#include <cuda_runtime.h>
#include <math.h>
#include <stdint.h>

#define B_SZ     128
#define L_Q      64
#define L_D      512
#define E_DIM    300
#define N_K      11
#define NTG      128        // docs per group
#define NGRP     2          // doc groups per CTA
#define NPAIR    2          // grid.x
#define NTHREADS 256
#define KC       64         // k per pipeline chunk
#define GC       5          // chunks per group (5*64 = 320 >= 300)
#define NCC      10         // total chunks per CTA
#define SW       68         // smem row stride (words): 68%32=4 -> conflict-free

// smem word offsets
#define BUF_W     13056     // A 64*68 + B 128*68
#define BOFF_B    4352
#define OFF_MASKD (2 * BUF_W)          // 256
#define OFF_SS    (OFF_MASKD + 256)    // 192 sumsq
#define OFF_INV   (OFF_SS + 192)       // 192 inverse norms (q:0..63, d:64..191)
#define OFF_POOL  (OFF_INV + 192)      // 704
#define OFF_RED   (OFF_POOL + 704)     // 64
#define SMEM_WORDS (OFF_RED + 64)
#define SMEM_BYTES (SMEM_WORDS * 4)    // 110080 B -> 2 CTAs fit in 228KB

#define TF32_MASK 0xFFFFE000u   // the bits mma.tf32 actually keeps (RZ truncation)

__device__ float g_pool[B_SZ * NPAIR * L_Q * N_K];
__device__ unsigned int g_cnt[B_SZ];   // zero-init; last CTA resets (graph-replay safe)

__device__ __forceinline__ uint32_t smem_u32(const void* p) {
    uint32_t a;
    asm("{ .reg .u64 t; cvta.to.shared.u64 t, %1; cvt.u32.u64 %0, t; }" : "=r"(a) : "l"(p));
    return a;
}
__device__ __forceinline__ void mma_tf32(float* c, const uint32_t* a, uint32_t b0, uint32_t b1) {
    asm volatile("mma.sync.aligned.m16n8k8.row.col.f32.tf32.tf32.f32 "
        "{%0,%1,%2,%3},{%4,%5,%6,%7},{%8,%9},{%0,%1,%2,%3};"
        : "+f"(c[0]), "+f"(c[1]), "+f"(c[2]), "+f"(c[3])
        : "r"(a[0]), "r"(a[1]), "r"(a[2]), "r"(a[3]), "r"(b0), "r"(b1));
}
__device__ __forceinline__ void cp16(uint32_t dst, const void* src, int sz) {
    asm volatile("cp.async.cg.shared.global [%0], [%1], 16, %2;"
        :: "r"(dst), "l"(src), "r"(sz) : "memory");
}
#define CP_COMMIT() asm volatile("cp.async.commit_group;" ::: "memory")
#define CP_WAIT0()  asm volatile("cp.async.wait_group 0;" ::: "memory")

__device__ __forceinline__ float rcpa(float x) {
    float r; asm("rcp.approx.f32 %0,%1;" : "=f"(r) : "f"(x)); return r;
}
// 2^y for y in [-126, 15], pure fma/alu, err ~2e-6
__device__ __forceinline__ float exp2ff(float y) {
    float z = __fadd_rn(y, 12582912.0f);
    float f = __fadd_rn(y, -__fadd_rn(z, -12582912.0f));
    float p =              1.3333558e-3f;
    p = fmaf(p, f, 9.6181293e-3f);
    p = fmaf(p, f, 5.5504109e-2f);
    p = fmaf(p, f, 2.4022650e-1f);
    p = fmaf(p, f, 6.9314718e-1f);
    p = fmaf(p, f, 1.0f);
    int n = __float_as_int(z) - 0x4B400000;
    return p * __int_as_float((n + 127) << 23);
}

__global__ __launch_bounds__(NTHREADS, 2)
void knrm_tf32(const float* __restrict__ q,
               const float* __restrict__ d,
               const float* __restrict__ mq,
               const float* __restrict__ md,
               const float* __restrict__ w,
               const float* __restrict__ bias,
               float* __restrict__ out)
{
    extern __shared__ float smf[];
    __shared__ int s_last;

    float* s_maskd = smf + OFF_MASKD;   // 256 docs (both groups)
    float* s_ss    = smf + OFF_SS;
    float* s_inv   = smf + OFF_INV;
    float* s_pool  = smf + OFF_POOL;
    float* s_red   = smf + OFF_RED;

    const uint32_t smb = smem_u32(smf);
    const int pair = blockIdx.x;        // 0..1
    const int b    = blockIdx.y;
    const int tid  = threadIdx.x;
    const int lane = tid & 31;
    const int warp = tid >> 5;
    const int wm   = warp >> 2;
    const int wn   = warp & 3;
    const int qrow = lane >> 2;
    const int c4   = lane & 3;

    const float* __restrict__ qb = q + (size_t)b * L_Q * E_DIM;
    const float* __restrict__ db = d + (size_t)b * L_D * E_DIM;

    for (int i = tid; i < NGRP * NTG; i += NTHREADS)
        s_maskd[i] = md[b * L_D + pair * NGRP * NTG + i];
    for (int i = tid; i < L_Q * N_K; i += NTHREADS) s_pool[i] = 0.f;
    __syncthreads();

    // ---- staging geometry: thread owns (row16-lane, 16B quad); slots at const offsets ----
    const int qrow16 = tid >> 4;        // 0..15
    const int quad   = tid & 15;        // 0..15
    const int koff   = quad * 4;        // 0..60
    const float* baseA = qb + (size_t)qrow16 * E_DIM + koff;
    const float* baseB = db + (size_t)(pair * NGRP * NTG + qrow16) * E_DIM + koff;
    const uint32_t dbaseA = smb + (qrow16 * SW + quad * 4) * 4;
    const uint32_t dbaseB = smb + (BOFF_B + qrow16 * SW + quad * 4) * 4;

    const int offA0 = (wm * 32 + qrow) * SW;
    int offB[4];
    #pragma unroll
    for (int nt = 0; nt < 4; ++nt) offB[nt] = BOFF_B + (wn * 32 + nt * 8 + qrow) * SW;

    float acc[2][4][4];
    #pragma unroll
    for (int mt = 0; mt < 2; ++mt)
        #pragma unroll
        for (int nt = 0; nt < 4; ++nt)
            #pragma unroll
            for (int c = 0; c < 4; ++c) acc[mt][nt][c] = 0.f;
    float ssA[4], ssB[4];
    #pragma unroll
    for (int i = 0; i < 4; ++i) { ssA[i] = 0.f; ssB[i] = 0.f; }

    // issue chunk cc: 4 A-slots + 8 B-slots, all const-offset from two bases
    #define ISSUE_CHUNK(cc) do {                                             \
        const int kb_   = ((cc) % GC) * KC;                                  \
        const int goff_ = ((cc) >= GC) ? NTG * E_DIM : 0;                    \
        const uint32_t bsel_ = ((cc) & 1) * (BUF_W * 4);                     \
        const int sz_ = (kb_ + koff < E_DIM) ? 16 : 0;                       \
        const float* pA_ = baseA + (sz_ ? kb_ : 0);                          \
        const float* pB_ = baseB + (sz_ ? (kb_ + goff_) : 0);                \
        _Pragma("unroll")                                                    \
        for (int i_ = 0; i_ < 4; ++i_)                                       \
            cp16(dbaseA + bsel_ + i_ * (16 * SW * 4), pA_ + i_ * (16 * E_DIM), sz_); \
        _Pragma("unroll")                                                    \
        for (int j_ = 0; j_ < 8; ++j_)                                       \
            cp16(dbaseB + bsel_ + j_ * (16 * SW * 4), pB_ + j_ * (16 * E_DIM), sz_); \
        CP_COMMIT();                                                         \
    } while (0)

    ISSUE_CHUNK(0);

    #pragma unroll 1
    for (int cc = 0; cc < NCC; ++cc) {
        CP_WAIT0();            // chunk cc resident
        __syncthreads();       // visible to all; prior readers of other buffer done
        if (cc + 1 < NCC) ISSUE_CHUNK(cc + 1);

        // ---- MMA on chunk cc (raw fp32 words; HW truncates to tf32) ----
        const uint32_t* bw = (const uint32_t*)(smf + (cc & 1) * BUF_W);
        #pragma unroll
        for (int s = 0; s < 8; ++s) {
            const int kc = s * 8 + c4;
            uint32_t a[2][4];
            #pragma unroll
            for (int mt = 0; mt < 2; ++mt) {
                const int oa = offA0 + mt * 16 * SW + kc;
                a[mt][0] = bw[oa];
                a[mt][1] = bw[oa + 8 * SW];
                a[mt][2] = bw[oa + 4];
                a[mt][3] = bw[oa + 8 * SW + 4];
            }
            uint32_t bf[4][2];
            #pragma unroll
            for (int nt = 0; nt < 4; ++nt) {
                bf[nt][0] = bw[offB[nt] + kc];
                bf[nt][1] = bw[offB[nt] + kc + 4];
            }
            // norms on the TRUNCATED words (what the MMA actually sees) ->
            // systematic tf32-truncation bias cancels in the cosine.
            if (wn == 0) {
                #pragma unroll
                for (int mt = 0; mt < 2; ++mt) {
                    float a0 = __uint_as_float(a[mt][0] & TF32_MASK);
                    float a1 = __uint_as_float(a[mt][1] & TF32_MASK);
                    float a2 = __uint_as_float(a[mt][2] & TF32_MASK);
                    float a3 = __uint_as_float(a[mt][3] & TF32_MASK);
                    ssA[mt * 2 + 0] = fmaf(a0, a0, fmaf(a2, a2, ssA[mt * 2 + 0]));
                    ssA[mt * 2 + 1] = fmaf(a1, a1, fmaf(a3, a3, ssA[mt * 2 + 1]));
                }
            }
            if (wm == 0) {
                #pragma unroll
                for (int nt = 0; nt < 4; ++nt) {
                    float b0 = __uint_as_float(bf[nt][0] & TF32_MASK);
                    float b1 = __uint_as_float(bf[nt][1] & TF32_MASK);
                    ssB[nt] = fmaf(b0, b0, fmaf(b1, b1, ssB[nt]));
                }
            }
            #pragma unroll
            for (int mt = 0; mt < 2; ++mt)
                #pragma unroll
                for (int nt = 0; nt < 4; ++nt)
                    mma_tf32(acc[mt][nt], a[mt], bf[nt][0], bf[nt][1]);
        }

        // ---- group epilogue: norms + pooling ----
        if ((cc % GC) == (GC - 1)) {
            const int g = cc / GC;
            #pragma unroll
            for (int i = 0; i < 4; ++i) {
                ssA[i] += __shfl_xor_sync(0xffffffffu, ssA[i], 1);
                ssA[i] += __shfl_xor_sync(0xffffffffu, ssA[i], 2);
                ssB[i] += __shfl_xor_sync(0xffffffffu, ssB[i], 1);
                ssB[i] += __shfl_xor_sync(0xffffffffu, ssB[i], 2);
            }
            if (c4 == 0) {
                if (wn == 0) {
                    #pragma unroll
                    for (int mt = 0; mt < 2; ++mt)
                        #pragma unroll
                        for (int rh = 0; rh < 2; ++rh)
                            s_ss[wm * 32 + mt * 16 + rh * 8 + qrow] = ssA[mt * 2 + rh];
                }
                if (wm == 0) {
                    #pragma unroll
                    for (int nt = 0; nt < 4; ++nt)
                        s_ss[64 + wn * 32 + nt * 8 + qrow] = ssB[nt];
                }
            }
            __syncthreads();
            if (tid < 192) s_inv[tid] = 1.0f / fmaxf(sqrtf(s_ss[tid]), 1e-12f);
            __syncthreads();

            float ivd[8], mvd[8];
            #pragma unroll
            for (int nt = 0; nt < 4; ++nt)
                #pragma unroll
                for (int cm = 0; cm < 2; ++cm) {
                    const int nl = wn * 32 + nt * 8 + c4 * 2 + cm;
                    ivd[nt * 2 + cm] = s_inv[64 + nl];
                    mvd[nt * 2 + cm] = s_maskd[g * NTG + nl];
                }
            #pragma unroll
            for (int mt = 0; mt < 2; ++mt) {
                #pragma unroll
                for (int rh = 0; rh < 2; ++rh) {
                    const int row = wm * 32 + mt * 16 + qrow + rh * 8;
                    const float iq = s_inv[row];
                    float pl[N_K];
                    #pragma unroll
                    for (int k = 0; k < N_K; ++k) pl[k] = 0.f;
                    #pragma unroll
                    for (int nt = 0; nt < 4; ++nt) {
                        #pragma unroll
                        for (int cm = 0; cm < 2; ++cm) {
                            const float s  = acc[mt][nt][rh * 2 + cm] * iq * ivd[nt * 2 + cm];
                            const float mv = mvd[nt * 2 + cm];
                            const float base = exp2ff(fmaxf(s * s * -72.134752f, -126.f));
                            const float t    = exp2ff(s * 14.4269504f);
                            const float r    = rcpa(t);
                            const float t2 = t * t, r2 = r * r;
                            const float A1 = (base * t) * 0.60653066f;
                            const float A3 = (A1 * t2) * 0.018315639f;
                            const float A5 = (A3 * t2) * 3.3546263e-4f;
                            const float A7 = (A5 * t2) * 6.1442124e-6f;
                            const float A9 = (A7 * t2) * 1.1253517e-7f;
                            const float B1 = (base * r) * 0.60653066f;
                            const float B3 = (B1 * r2) * 0.018315639f;
                            const float B5 = (B3 * r2) * 3.3546263e-4f;
                            const float B7 = (B5 * r2) * 6.1442124e-6f;
                            const float B9 = (B7 * r2) * 1.1253517e-7f;
                            pl[1]  = fmaf(mv, A9, pl[1]);
                            pl[2]  = fmaf(mv, A7, pl[2]);
                            pl[3]  = fmaf(mv, A5, pl[3]);
                            pl[4]  = fmaf(mv, A3, pl[4]);
                            pl[5]  = fmaf(mv, A1, pl[5]);
                            pl[6]  = fmaf(mv, B1, pl[6]);
                            pl[7]  = fmaf(mv, B3, pl[7]);
                            pl[8]  = fmaf(mv, B5, pl[8]);
                            pl[9]  = fmaf(mv, B7, pl[9]);
                            pl[10] = fmaf(mv, B9, pl[10]);
                            const float d1 = s - 1.0f;   // kernel 0: sigma=1e-3
                            if (fabsf(d1) < 0.0125f) {
                                const float u = d1 * 849.321802f;
                                pl[0] = fmaf(mv, exp2ff(fmaxf(-u * u, -126.f)), pl[0]);
                            }
                        }
                    }
                    #pragma unroll
                    for (int k = 0; k < N_K; ++k) {
                        float v = pl[k];
                        v += __shfl_xor_sync(0xffffffffu, v, 1);
                        v += __shfl_xor_sync(0xffffffffu, v, 2);
                        if (c4 == 0) atomicAdd(&s_pool[row * N_K + k], v);
                    }
                }
            }
            // reset accumulators for next group
            #pragma unroll
            for (int mt = 0; mt < 2; ++mt)
                #pragma unroll
                for (int nt = 0; nt < 4; ++nt)
                    #pragma unroll
                    for (int c = 0; c < 4; ++c) acc[mt][nt][c] = 0.f;
            #pragma unroll
            for (int i = 0; i < 4; ++i) { ssA[i] = 0.f; ssB[i] = 0.f; }
            __syncthreads();
        }
    }

    // ---- publish pair partials; last CTA of this batch finalizes ----
    float* gp = g_pool + (size_t)(b * NPAIR + pair) * (L_Q * N_K);
    for (int i = tid; i < L_Q * N_K; i += NTHREADS) gp[i] = s_pool[i];
    __threadfence();
    __syncthreads();
    if (tid == 0) {
        unsigned int t = atomicAdd(&g_cnt[b], 1u);
        s_last = (t == NPAIR - 1);
    }
    __syncthreads();

    if (s_last) {
        __threadfence();
        const float* gb = g_pool + (size_t)b * NPAIR * L_Q * N_K;
        for (int i = tid; i < L_Q * N_K; i += NTHREADS)
            s_pool[i] = gb[i] + gb[L_Q * N_K + i];
        __syncthreads();
        if (tid < L_Q) {
            const float mqv = mq[b * L_Q + tid] * 0.01f;
            float cm = 0.f;
            #pragma unroll
            for (int k = 0; k < N_K; ++k)
                cm = fmaf(logf(fmaxf(s_pool[tid * N_K + k], 1e-10f)) * mqv, w[k], cm);
            s_red[tid] = cm;
        }
        __syncthreads();
        if (tid == 0) {
            float s = bias[0];
            #pragma unroll
            for (int m = 0; m < L_Q; ++m) s += s_red[m];
            out[b] = tanhf(s);
            g_cnt[b] = 0;   // reset for next graph replay
        }
    }
}

extern "C" void kernel_launch(void* const* d_in, const int* in_sizes, int n_in,
                              void* d_out, int out_size) {
    const float* q    = (const float*)d_in[0];   // [B, Lq, E]
    const float* d    = (const float*)d_in[1];   // [B, Ld, E]
    const float* mq   = (const float*)d_in[2];   // [B, Lq]
    const float* md   = (const float*)d_in[3];   // [B, Ld]
    const float* w    = (const float*)d_in[4];   // [1, K]
    const float* bias = (const float*)d_in[5];   // [1]
    float* out = (float*)d_out;                  // [B, 1]

    cudaFuncSetAttribute(knrm_tf32, cudaFuncAttributeMaxDynamicSharedMemorySize, SMEM_BYTES);
    dim3 grid(NPAIR, B_SZ);
    knrm_tf32<<<grid, NTHREADS, SMEM_BYTES>>>(q, d, mq, md, w, bias, out);
}

// round 15
// speedup vs baseline: 1.0348x; 1.0348x over previous
#include <cuda_runtime.h>
#include <math.h>
#include <stdint.h>

#define B_SZ     128
#define L_Q      64
#define L_D      512
#define E_DIM    300
#define N_K      11
#define NDG      8          // doc-groups of 64 per batch; grid.x
#define DTG      64         // docs per CTA
#define NTHREADS 128
#define KC       32         // k per pipeline chunk
#define NCC      10         // chunks (10*32 = 320 >= 300)
#define SW       36         // smem row stride (words) -> conflict-free

// smem word offsets
#define BUF_W     4608      // (64 A-rows + 64 B-rows) * 36
#define BOFF_B    2304      // 64*36
#define OFF_MASKD (2 * BUF_W)          // 64
#define OFF_SS    (OFF_MASKD + 64)     // 128 sumsq (q:0..63, d:64..127)
#define OFF_INV   (OFF_SS + 128)       // 128
#define OFF_POOL  (OFF_INV + 128)      // 704
#define OFF_RED   (OFF_POOL + 704)     // 64
#define SMEM_WORDS (OFF_RED + 64)
#define SMEM_BYTES (SMEM_WORDS * 4)    // 41216 B -> 5 CTAs/SM by smem

#define TF32_MASK 0xFFFFE000u   // bits mma.tf32 actually keeps (RZ truncation)

__device__ float g_pool[B_SZ * NDG * L_Q * N_K];
__device__ unsigned int g_cnt[B_SZ];   // zero-init; last CTA resets (graph-replay safe)

__device__ __forceinline__ uint32_t smem_u32(const void* p) {
    uint32_t a;
    asm("{ .reg .u64 t; cvta.to.shared.u64 t, %1; cvt.u32.u64 %0, t; }" : "=r"(a) : "l"(p));
    return a;
}
__device__ __forceinline__ void mma_tf32(float* c, const uint32_t* a, uint32_t b0, uint32_t b1) {
    asm volatile("mma.sync.aligned.m16n8k8.row.col.f32.tf32.tf32.f32 "
        "{%0,%1,%2,%3},{%4,%5,%6,%7},{%8,%9},{%0,%1,%2,%3};"
        : "+f"(c[0]), "+f"(c[1]), "+f"(c[2]), "+f"(c[3])
        : "r"(a[0]), "r"(a[1]), "r"(a[2]), "r"(a[3]), "r"(b0), "r"(b1));
}
__device__ __forceinline__ void cp16(uint32_t dst, const void* src, int sz) {
    asm volatile("cp.async.cg.shared.global [%0], [%1], 16, %2;"
        :: "r"(dst), "l"(src), "r"(sz) : "memory");
}
#define CP_COMMIT() asm volatile("cp.async.commit_group;" ::: "memory")
#define CP_WAIT0()  asm volatile("cp.async.wait_group 0;" ::: "memory")

__device__ __forceinline__ float rcpa(float x) {
    float r; asm("rcp.approx.f32 %0,%1;" : "=f"(r) : "f"(x)); return r;
}
__device__ __forceinline__ float ex2a(float x) {   // MUFU 2^x
    float r; asm("ex2.approx.f32 %0,%1;" : "=f"(r) : "f"(x)); return r;
}

__global__ __launch_bounds__(NTHREADS, 5)
void knrm_tf32(const float* __restrict__ q,
               const float* __restrict__ d,
               const float* __restrict__ mq,
               const float* __restrict__ md,
               const float* __restrict__ w,
               const float* __restrict__ bias,
               float* __restrict__ out)
{
    extern __shared__ float smf[];
    __shared__ int s_last;

    float* s_maskd = smf + OFF_MASKD;   // 64 docs
    float* s_ss    = smf + OFF_SS;
    float* s_inv   = smf + OFF_INV;
    float* s_pool  = smf + OFF_POOL;
    float* s_red   = smf + OFF_RED;

    const uint32_t smb = smem_u32(smf);
    const int dg   = blockIdx.x;        // 0..7
    const int b    = blockIdx.y;
    const int tid  = threadIdx.x;       // 0..127
    const int lane = tid & 31;
    const int warp = tid >> 5;          // 0..3
    const int wm   = warp >> 1;         // 0..1 : q rows wm*32
    const int wn   = warp & 1;          // 0..1 : doc cols wn*32
    const int qrow = lane >> 2;
    const int c4   = lane & 3;

    const float* __restrict__ qb = q + (size_t)b * L_Q * E_DIM;
    const float* __restrict__ db = d + (size_t)b * L_D * E_DIM;

    for (int i = tid; i < DTG; i += NTHREADS)
        s_maskd[i] = md[b * L_D + dg * DTG + i];
    for (int i = tid; i < L_Q * N_K; i += NTHREADS) s_pool[i] = 0.f;
    __syncthreads();

    // ---- staging geometry: thread owns (row16-lane, 16B quad) ----
    const int r0   = tid >> 3;          // 0..15
    const int quad = tid & 7;           // 0..7
    const int koff = quad * 4;          // 0..28 (< KC always)
    const float* baseA = qb + (size_t)r0 * E_DIM + koff;
    const float* baseB = db + (size_t)(dg * DTG + r0) * E_DIM + koff;
    const uint32_t dbaseA = smb + (r0 * SW + quad * 4) * 4;
    const uint32_t dbaseB = smb + (BOFF_B + r0 * SW + quad * 4) * 4;

    const int offA0 = (wm * 32 + qrow) * SW;
    int offB[4];
    #pragma unroll
    for (int nt = 0; nt < 4; ++nt) offB[nt] = BOFF_B + (wn * 32 + nt * 8 + qrow) * SW;

    float acc[2][4][4];
    #pragma unroll
    for (int mt = 0; mt < 2; ++mt)
        #pragma unroll
        for (int nt = 0; nt < 4; ++nt)
            #pragma unroll
            for (int c = 0; c < 4; ++c) acc[mt][nt][c] = 0.f;
    float ssA[4], ssB[4];
    #pragma unroll
    for (int i = 0; i < 4; ++i) { ssA[i] = 0.f; ssB[i] = 0.f; }

    // issue chunk cc: 4 A-slots + 4 B-slots at constant offsets
    #define ISSUE_CHUNK(cc) do {                                               \
        const int kb_ = (cc) * KC;                                             \
        const uint32_t bsel_ = ((cc) & 1) * (BUF_W * 4);                       \
        const int sz_ = (kb_ + koff < E_DIM) ? 16 : 0;                         \
        const float* pA_ = baseA + (sz_ ? kb_ : 0);                            \
        const float* pB_ = baseB + (sz_ ? kb_ : 0);                            \
        _Pragma("unroll")                                                      \
        for (int i_ = 0; i_ < 4; ++i_) {                                       \
            cp16(dbaseA + bsel_ + i_ * (16 * SW * 4), pA_ + i_ * (16 * E_DIM), sz_); \
            cp16(dbaseB + bsel_ + i_ * (16 * SW * 4), pB_ + i_ * (16 * E_DIM), sz_); \
        }                                                                      \
        CP_COMMIT();                                                           \
    } while (0)

    ISSUE_CHUNK(0);

    #pragma unroll 1
    for (int cc = 0; cc < NCC; ++cc) {
        CP_WAIT0();
        __syncthreads();
        if (cc + 1 < NCC) ISSUE_CHUNK(cc + 1);

        // ---- MMA on chunk cc (raw fp32 words; HW truncates to tf32) ----
        const uint32_t* bw = (const uint32_t*)(smf + (cc & 1) * BUF_W);
        #pragma unroll
        for (int s = 0; s < 4; ++s) {
            const int kc = s * 8 + c4;
            uint32_t a[2][4];
            #pragma unroll
            for (int mt = 0; mt < 2; ++mt) {
                const int oa = offA0 + mt * 16 * SW + kc;
                a[mt][0] = bw[oa];
                a[mt][1] = bw[oa + 8 * SW];
                a[mt][2] = bw[oa + 4];
                a[mt][3] = bw[oa + 8 * SW + 4];
            }
            uint32_t bf[4][2];
            #pragma unroll
            for (int nt = 0; nt < 4; ++nt) {
                bf[nt][0] = bw[offB[nt] + kc];
                bf[nt][1] = bw[offB[nt] + kc + 4];
            }
            // norms on the TRUNCATED words -> tf32 bias cancels in the cosine
            if (wn == 0) {
                #pragma unroll
                for (int mt = 0; mt < 2; ++mt) {
                    float a0 = __uint_as_float(a[mt][0] & TF32_MASK);
                    float a1 = __uint_as_float(a[mt][1] & TF32_MASK);
                    float a2 = __uint_as_float(a[mt][2] & TF32_MASK);
                    float a3 = __uint_as_float(a[mt][3] & TF32_MASK);
                    ssA[mt * 2 + 0] = fmaf(a0, a0, fmaf(a2, a2, ssA[mt * 2 + 0]));
                    ssA[mt * 2 + 1] = fmaf(a1, a1, fmaf(a3, a3, ssA[mt * 2 + 1]));
                }
            }
            if (wm == 0) {
                #pragma unroll
                for (int nt = 0; nt < 4; ++nt) {
                    float b0 = __uint_as_float(bf[nt][0] & TF32_MASK);
                    float b1 = __uint_as_float(bf[nt][1] & TF32_MASK);
                    ssB[nt] = fmaf(b0, b0, fmaf(b1, b1, ssB[nt]));
                }
            }
            #pragma unroll
            for (int mt = 0; mt < 2; ++mt)
                #pragma unroll
                for (int nt = 0; nt < 4; ++nt)
                    mma_tf32(acc[mt][nt], a[mt], bf[nt][0], bf[nt][1]);
        }
    }

    // ---- norms ----
    #pragma unroll
    for (int i = 0; i < 4; ++i) {
        ssA[i] += __shfl_xor_sync(0xffffffffu, ssA[i], 1);
        ssA[i] += __shfl_xor_sync(0xffffffffu, ssA[i], 2);
        ssB[i] += __shfl_xor_sync(0xffffffffu, ssB[i], 1);
        ssB[i] += __shfl_xor_sync(0xffffffffu, ssB[i], 2);
    }
    if (c4 == 0) {
        if (wn == 0) {
            #pragma unroll
            for (int mt = 0; mt < 2; ++mt)
                #pragma unroll
                for (int rh = 0; rh < 2; ++rh)
                    s_ss[wm * 32 + mt * 16 + rh * 8 + qrow] = ssA[mt * 2 + rh];
        }
        if (wm == 0) {
            #pragma unroll
            for (int nt = 0; nt < 4; ++nt)
                s_ss[64 + wn * 32 + nt * 8 + qrow] = ssB[nt];
        }
    }
    __syncthreads();
    if (tid < 128) s_inv[tid] = 1.0f / fmaxf(sqrtf(s_ss[tid]), 1e-12f);
    __syncthreads();

    // ---- pooling from fragments (exponentials on MUFU) ----
    float ivd[8], mvd[8];
    #pragma unroll
    for (int nt = 0; nt < 4; ++nt)
        #pragma unroll
        for (int cm = 0; cm < 2; ++cm) {
            const int nl = wn * 32 + nt * 8 + c4 * 2 + cm;
            ivd[nt * 2 + cm] = s_inv[64 + nl];
            mvd[nt * 2 + cm] = s_maskd[nl];
        }
    #pragma unroll
    for (int mt = 0; mt < 2; ++mt) {
        #pragma unroll
        for (int rh = 0; rh < 2; ++rh) {
            const int row = wm * 32 + mt * 16 + qrow + rh * 8;
            const float iq = s_inv[row];
            float pl[N_K];
            #pragma unroll
            for (int k = 0; k < N_K; ++k) pl[k] = 0.f;
            #pragma unroll
            for (int nt = 0; nt < 4; ++nt) {
                #pragma unroll
                for (int cm = 0; cm < 2; ++cm) {
                    const float s  = acc[mt][nt][rh * 2 + cm] * iq * ivd[nt * 2 + cm];
                    const float mv = mvd[nt * 2 + cm];
                    const float base = ex2a(fmaxf(s * s * -72.134752f, -126.f)); // e^{-50 s^2}
                    const float t    = ex2a(s * 14.4269504f);                    // e^{10 s}
                    const float r    = rcpa(t);
                    const float t2 = t * t, r2 = r * r;
                    const float A1 = (base * t) * 0.60653066f;
                    const float A3 = (A1 * t2) * 0.018315639f;
                    const float A5 = (A3 * t2) * 3.3546263e-4f;
                    const float A7 = (A5 * t2) * 6.1442124e-6f;
                    const float A9 = (A7 * t2) * 1.1253517e-7f;
                    const float B1 = (base * r) * 0.60653066f;
                    const float B3 = (B1 * r2) * 0.018315639f;
                    const float B5 = (B3 * r2) * 3.3546263e-4f;
                    const float B7 = (B5 * r2) * 6.1442124e-6f;
                    const float B9 = (B7 * r2) * 1.1253517e-7f;
                    pl[1]  = fmaf(mv, A9, pl[1]);
                    pl[2]  = fmaf(mv, A7, pl[2]);
                    pl[3]  = fmaf(mv, A5, pl[3]);
                    pl[4]  = fmaf(mv, A3, pl[4]);
                    pl[5]  = fmaf(mv, A1, pl[5]);
                    pl[6]  = fmaf(mv, B1, pl[6]);
                    pl[7]  = fmaf(mv, B3, pl[7]);
                    pl[8]  = fmaf(mv, B5, pl[8]);
                    pl[9]  = fmaf(mv, B7, pl[9]);
                    pl[10] = fmaf(mv, B9, pl[10]);
                    const float d1 = s - 1.0f;   // kernel 0: sigma=1e-3
                    if (fabsf(d1) < 0.0125f) {
                        const float u = d1 * 849.321802f;
                        pl[0] = fmaf(mv, ex2a(fmaxf(-u * u, -126.f)), pl[0]);
                    }
                }
            }
            #pragma unroll
            for (int k = 0; k < N_K; ++k) {
                float v = pl[k];
                v += __shfl_xor_sync(0xffffffffu, v, 1);
                v += __shfl_xor_sync(0xffffffffu, v, 2);
                if (c4 == 0) atomicAdd(&s_pool[row * N_K + k], v);
            }
        }
    }
    __syncthreads();

    // ---- publish doc-group partials; last CTA of this batch finalizes ----
    float* gp = g_pool + (size_t)(b * NDG + dg) * (L_Q * N_K);
    for (int i = tid; i < L_Q * N_K; i += NTHREADS) gp[i] = s_pool[i];
    __threadfence();
    __syncthreads();
    if (tid == 0) {
        unsigned int t = atomicAdd(&g_cnt[b], 1u);
        s_last = (t == NDG - 1);
    }
    __syncthreads();

    if (s_last) {
        __threadfence();
        const float* gb = g_pool + (size_t)b * NDG * L_Q * N_K;
        for (int i = tid; i < L_Q * N_K; i += NTHREADS) {
            float v = 0.f;
            #pragma unroll
            for (int c = 0; c < NDG; ++c) v += gb[c * (L_Q * N_K) + i];
            s_pool[i] = v;
        }
        __syncthreads();
        if (tid < L_Q) {
            const float mqv = mq[b * L_Q + tid] * 0.01f;
            float cm = 0.f;
            #pragma unroll
            for (int k = 0; k < N_K; ++k)
                cm = fmaf(logf(fmaxf(s_pool[tid * N_K + k], 1e-10f)) * mqv, w[k], cm);
            s_red[tid] = cm;
        }
        __syncthreads();
        if (tid == 0) {
            float s = bias[0];
            #pragma unroll
            for (int m = 0; m < L_Q; ++m) s += s_red[m];
            out[b] = tanhf(s);
            g_cnt[b] = 0;   // reset for next graph replay
        }
    }
}

extern "C" void kernel_launch(void* const* d_in, const int* in_sizes, int n_in,
                              void* d_out, int out_size) {
    const float* q    = (const float*)d_in[0];   // [B, Lq, E]
    const float* d    = (const float*)d_in[1];   // [B, Ld, E]
    const float* mq   = (const float*)d_in[2];   // [B, Lq]
    const float* md   = (const float*)d_in[3];   // [B, Ld]
    const float* w    = (const float*)d_in[4];   // [1, K]
    const float* bias = (const float*)d_in[5];   // [1]
    float* out = (float*)d_out;                  // [B, 1]

    cudaFuncSetAttribute(knrm_tf32, cudaFuncAttributeMaxDynamicSharedMemorySize, SMEM_BYTES);
    dim3 grid(NDG, B_SZ);
    knrm_tf32<<<grid, NTHREADS, SMEM_BYTES>>>(q, d, mq, md, w, bias, out);
}

// round 16
// speedup vs baseline: 1.0497x; 1.0145x over previous
#include <cuda_runtime.h>
#include <math.h>
#include <stdint.h>

#define B_SZ     128
#define L_Q      64
#define L_D      512
#define E_DIM    300
#define N_K      11
#define NDG      8          // doc-groups of 64 per batch; grid.x
#define DTG      64         // docs per CTA
#define NTHREADS 128
#define KC       32         // k per pipeline chunk
#define NCC      10         // chunks (10*32 = 320 >= 300)
#define SW       36         // smem row stride (words) -> conflict-free (LDSM: 144B stride)

// smem word offsets
#define BUF_W     4608      // (64 A-rows + 64 B-rows) * 36
#define BOFF_B    2304      // 64*36
#define OFF_MASKD (2 * BUF_W)          // 64
#define OFF_SS    (OFF_MASKD + 64)     // 128 sumsq (q:0..63, d:64..127)
#define OFF_INV   (OFF_SS + 128)       // 128
#define OFF_POOL  (OFF_INV + 128)      // 704
#define OFF_RED   (OFF_POOL + 704)     // 64
#define SMEM_WORDS (OFF_RED + 64)
#define SMEM_BYTES (SMEM_WORDS * 4)    // 41216 B -> 5 CTAs/SM by smem

#define TF32_MASK 0xFFFFE000u   // bits mma.tf32 actually keeps (RZ truncation)

typedef unsigned long long u64;

__device__ float g_pool[B_SZ * NDG * L_Q * N_K];
__device__ unsigned int g_cnt[B_SZ];   // zero-init; last CTA resets (graph-replay safe)

__device__ __forceinline__ uint32_t smem_u32(const void* p) {
    uint32_t a;
    asm("{ .reg .u64 t; cvta.to.shared.u64 t, %1; cvt.u32.u64 %0, t; }" : "=r"(a) : "l"(p));
    return a;
}
__device__ __forceinline__ void mma_tf32(float* c, const uint32_t* a, uint32_t b0, uint32_t b1) {
    asm volatile("mma.sync.aligned.m16n8k8.row.col.f32.tf32.tf32.f32 "
        "{%0,%1,%2,%3},{%4,%5,%6,%7},{%8,%9},{%0,%1,%2,%3};"
        : "+f"(c[0]), "+f"(c[1]), "+f"(c[2]), "+f"(c[3])
        : "r"(a[0]), "r"(a[1]), "r"(a[2]), "r"(a[3]), "r"(b0), "r"(b1));
}
// 8x8 b16 ldmatrix == 8x4 tf32 tile: each thread receives one full tf32 word
// at (row=lane/4, col=lane%4) -- exactly the mma.tf32 fragment layout.
__device__ __forceinline__ void ldm_x4(uint32_t* r, uint32_t addr) {
    asm volatile("ldmatrix.sync.aligned.m8n8.x4.shared.b16 {%0,%1,%2,%3}, [%4];"
        : "=r"(r[0]), "=r"(r[1]), "=r"(r[2]), "=r"(r[3]) : "r"(addr));
}
__device__ __forceinline__ void cp16(uint32_t dst, const void* src, int sz) {
    asm volatile("cp.async.cg.shared.global [%0], [%1], 16, %2;"
        :: "r"(dst), "l"(src), "r"(sz) : "memory");
}
#define CP_COMMIT() asm volatile("cp.async.commit_group;" ::: "memory")
#define CP_WAIT0()  asm volatile("cp.async.wait_group 0;" ::: "memory")

__device__ __forceinline__ float rcpa(float x) {
    float r; asm("rcp.approx.f32 %0,%1;" : "=f"(r) : "f"(x)); return r;
}
__device__ __forceinline__ float ex2a(float x) {   // MUFU 2^x
    float r; asm("ex2.approx.f32 %0,%1;" : "=f"(r) : "f"(x)); return r;
}
// packed f32x2 helpers (Blackwell dual-fp32 pipe)
__device__ __forceinline__ u64 pk2(float lo, float hi) {
    u64 r; asm("mov.b64 %0,{%1,%2};" : "=l"(r) : "f"(lo), "f"(hi)); return r;
}
__device__ __forceinline__ void upk2(float& lo, float& hi, u64 v) {
    asm("mov.b64 {%0,%1},%2;" : "=f"(lo), "=f"(hi) : "l"(v));
}
__device__ __forceinline__ u64 mul2(u64 a, u64 b) {
    u64 r; asm("mul.rn.f32x2 %0,%1,%2;" : "=l"(r) : "l"(a), "l"(b)); return r;
}
__device__ __forceinline__ u64 fma2(u64 a, u64 b, u64 c) {
    u64 r; asm("fma.rn.f32x2 %0,%1,%2,%3;" : "=l"(r) : "l"(a), "l"(b), "l"(c)); return r;
}

__global__ __launch_bounds__(NTHREADS, 5)
void knrm_tf32(const float* __restrict__ q,
               const float* __restrict__ d,
               const float* __restrict__ mq,
               const float* __restrict__ md,
               const float* __restrict__ w,
               const float* __restrict__ bias,
               float* __restrict__ out)
{
    extern __shared__ float smf[];
    __shared__ int s_last;

    float* s_maskd = smf + OFF_MASKD;
    float* s_ss    = smf + OFF_SS;
    float* s_inv   = smf + OFF_INV;
    float* s_pool  = smf + OFF_POOL;
    float* s_red   = smf + OFF_RED;

    const uint32_t smb = smem_u32(smf);
    const int dg   = blockIdx.x;
    const int b    = blockIdx.y;
    const int tid  = threadIdx.x;
    const int lane = tid & 31;
    const int warp = tid >> 5;          // 0..3
    const int wm   = warp >> 1;         // 0..1 : q rows wm*32
    const int wn   = warp & 1;          // 0..1 : doc cols wn*32
    const int qrow = lane >> 2;
    const int c4   = lane & 3;

    const float* __restrict__ qb = q + (size_t)b * L_Q * E_DIM;
    const float* __restrict__ db = d + (size_t)b * L_D * E_DIM;

    for (int i = tid; i < DTG; i += NTHREADS)
        s_maskd[i] = md[b * L_D + dg * DTG + i];
    for (int i = tid; i < L_Q * N_K; i += NTHREADS) s_pool[i] = 0.f;
    __syncthreads();

    // ---- staging geometry: thread owns (row16-lane, 16B quad) ----
    const int r0   = tid >> 3;
    const int quad = tid & 7;
    const int koff = quad * 4;
    const float* baseA = qb + (size_t)r0 * E_DIM + koff;
    const float* baseB = db + (size_t)(dg * DTG + r0) * E_DIM + koff;
    const uint32_t dbaseA = smb + (r0 * SW + quad * 4) * 4;
    const uint32_t dbaseB = smb + (BOFF_B + r0 * SW + quad * 4) * 4;

    // ---- ldmatrix per-lane row addresses (buffer 0, s = 0) ----
    const int l15 = lane & 15;
    const int l7  = lane & 7;
    uint32_t aAddr[2], bAddr[2];
    #pragma unroll
    for (int mt = 0; mt < 2; ++mt)
        aAddr[mt] = smb + (((wm * 32 + mt * 16 + l15) * SW) + ((lane >> 4) << 2)) * 4;
    #pragma unroll
    for (int p = 0; p < 2; ++p)
        bAddr[p] = smb + ((BOFF_B + (wn * 32 + (p * 2 + ((lane >> 4) & 1)) * 8 + l7) * SW)
                          + (((lane >> 3) & 1) << 2)) * 4;

    float acc[2][4][4];
    #pragma unroll
    for (int mt = 0; mt < 2; ++mt)
        #pragma unroll
        for (int nt = 0; nt < 4; ++nt)
            #pragma unroll
            for (int c = 0; c < 4; ++c) acc[mt][nt][c] = 0.f;
    float ssA[4], ssB[4];
    #pragma unroll
    for (int i = 0; i < 4; ++i) { ssA[i] = 0.f; ssB[i] = 0.f; }

    #define ISSUE_CHUNK(cc) do {                                               \
        const int kb_ = (cc) * KC;                                             \
        const uint32_t bsel_ = ((cc) & 1) * (BUF_W * 4);                       \
        const int sz_ = (kb_ + koff < E_DIM) ? 16 : 0;                         \
        const float* pA_ = baseA + (sz_ ? kb_ : 0);                            \
        const float* pB_ = baseB + (sz_ ? kb_ : 0);                            \
        _Pragma("unroll")                                                      \
        for (int i_ = 0; i_ < 4; ++i_) {                                       \
            cp16(dbaseA + bsel_ + i_ * (16 * SW * 4), pA_ + i_ * (16 * E_DIM), sz_); \
            cp16(dbaseB + bsel_ + i_ * (16 * SW * 4), pB_ + i_ * (16 * E_DIM), sz_); \
        }                                                                      \
        CP_COMMIT();                                                           \
    } while (0)

    ISSUE_CHUNK(0);

    #pragma unroll 1
    for (int cc = 0; cc < NCC; ++cc) {
        CP_WAIT0();
        __syncthreads();
        if (cc + 1 < NCC) ISSUE_CHUNK(cc + 1);

        const uint32_t bsel = (cc & 1) * (BUF_W * 4);
        #pragma unroll
        for (int s = 0; s < 4; ++s) {
            const uint32_t so = bsel + s * 32;
            uint32_t a[2][4], bb[2][4];
            ldm_x4(a[0], aAddr[0] + so);
            ldm_x4(a[1], aAddr[1] + so);
            ldm_x4(bb[0], bAddr[0] + so);   // {b0(nt0), b1(nt0), b0(nt1), b1(nt1)}
            ldm_x4(bb[1], bAddr[1] + so);   // {b0(nt2), b1(nt2), b0(nt3), b1(nt3)}

            // norms on the TRUNCATED words -> tf32 bias cancels in the cosine
            if (wn == 0) {
                #pragma unroll
                for (int mt = 0; mt < 2; ++mt) {
                    float a0 = __uint_as_float(a[mt][0] & TF32_MASK);
                    float a1 = __uint_as_float(a[mt][1] & TF32_MASK);
                    float a2 = __uint_as_float(a[mt][2] & TF32_MASK);
                    float a3 = __uint_as_float(a[mt][3] & TF32_MASK);
                    ssA[mt * 2 + 0] = fmaf(a0, a0, fmaf(a2, a2, ssA[mt * 2 + 0]));
                    ssA[mt * 2 + 1] = fmaf(a1, a1, fmaf(a3, a3, ssA[mt * 2 + 1]));
                }
            }
            if (wm == 0) {
                #pragma unroll
                for (int p = 0; p < 2; ++p) {
                    #pragma unroll
                    for (int j = 0; j < 2; ++j) {
                        float b0 = __uint_as_float(bb[p][j * 2 + 0] & TF32_MASK);
                        float b1 = __uint_as_float(bb[p][j * 2 + 1] & TF32_MASK);
                        ssB[p * 2 + j] = fmaf(b0, b0, fmaf(b1, b1, ssB[p * 2 + j]));
                    }
                }
            }
            #pragma unroll
            for (int mt = 0; mt < 2; ++mt)
                #pragma unroll
                for (int nt = 0; nt < 4; ++nt)
                    mma_tf32(acc[mt][nt], a[mt], bb[nt >> 1][(nt & 1) * 2],
                             bb[nt >> 1][(nt & 1) * 2 + 1]);
        }
    }

    // ---- norms ----
    #pragma unroll
    for (int i = 0; i < 4; ++i) {
        ssA[i] += __shfl_xor_sync(0xffffffffu, ssA[i], 1);
        ssA[i] += __shfl_xor_sync(0xffffffffu, ssA[i], 2);
        ssB[i] += __shfl_xor_sync(0xffffffffu, ssB[i], 1);
        ssB[i] += __shfl_xor_sync(0xffffffffu, ssB[i], 2);
    }
    if (c4 == 0) {
        if (wn == 0) {
            #pragma unroll
            for (int mt = 0; mt < 2; ++mt)
                #pragma unroll
                for (int rh = 0; rh < 2; ++rh)
                    s_ss[wm * 32 + mt * 16 + rh * 8 + qrow] = ssA[mt * 2 + rh];
        }
        if (wm == 0) {
            #pragma unroll
            for (int nt = 0; nt < 4; ++nt)
                s_ss[64 + wn * 32 + nt * 8 + qrow] = ssB[nt];
        }
    }
    __syncthreads();
    s_inv[tid] = 1.0f / fmaxf(sqrtf(s_ss[tid]), 1e-12f);
    __syncthreads();

    // ---- pooling from fragments: MUFU exps + packed f32x2 kernel chain ----
    const u64 K1 = pk2(0.60653066f,  0.60653066f);
    const u64 K3 = pk2(0.018315639f, 0.018315639f);
    const u64 K5 = pk2(3.3546263e-4f, 3.3546263e-4f);
    const u64 K7 = pk2(6.1442124e-6f, 6.1442124e-6f);
    const u64 K9 = pk2(1.1253517e-7f, 1.1253517e-7f);

    float ivd[8], mvd[8];
    u64 mvp[4];
    #pragma unroll
    for (int nt = 0; nt < 4; ++nt) {
        #pragma unroll
        for (int cm = 0; cm < 2; ++cm) {
            const int nl = wn * 32 + nt * 8 + c4 * 2 + cm;
            ivd[nt * 2 + cm] = s_inv[64 + nl];
            mvd[nt * 2 + cm] = s_maskd[nl];
        }
        mvp[nt] = pk2(mvd[nt * 2], mvd[nt * 2 + 1]);
    }
    #pragma unroll
    for (int mt = 0; mt < 2; ++mt) {
        #pragma unroll
        for (int rh = 0; rh < 2; ++rh) {
            const int row = wm * 32 + mt * 16 + qrow + rh * 8;
            const float iq = s_inv[row];
            u64 plp[N_K];
            #pragma unroll
            for (int k = 1; k < N_K; ++k) plp[k] = 0ULL;
            float pl0 = 0.f;
            #pragma unroll
            for (int nt = 0; nt < 4; ++nt) {
                const float s0 = acc[mt][nt][rh * 2 + 0] * iq * ivd[nt * 2 + 0];
                const float s1 = acc[mt][nt][rh * 2 + 1] * iq * ivd[nt * 2 + 1];
                const float e0 = ex2a(fmaxf(s0 * s0 * -72.134752f, -126.f));
                const float e1 = ex2a(fmaxf(s1 * s1 * -72.134752f, -126.f));
                const float t0 = ex2a(s0 * 14.4269504f);
                const float t1 = ex2a(s1 * 14.4269504f);
                const u64 bp = pk2(e0, e1);
                const u64 tp = pk2(t0, t1);
                const u64 rp = pk2(rcpa(t0), rcpa(t1));
                const u64 t2 = mul2(tp, tp), r2 = mul2(rp, rp);
                const u64 A1 = mul2(mul2(bp, tp), K1);
                const u64 A3 = mul2(mul2(A1, t2), K3);
                const u64 A5 = mul2(mul2(A3, t2), K5);
                const u64 A7 = mul2(mul2(A5, t2), K7);
                const u64 A9 = mul2(mul2(A7, t2), K9);
                const u64 B1 = mul2(mul2(bp, rp), K1);
                const u64 B3 = mul2(mul2(B1, r2), K3);
                const u64 B5 = mul2(mul2(B3, r2), K5);
                const u64 B7 = mul2(mul2(B5, r2), K7);
                const u64 B9 = mul2(mul2(B7, r2), K9);
                plp[1]  = fma2(A9, mvp[nt], plp[1]);
                plp[2]  = fma2(A7, mvp[nt], plp[2]);
                plp[3]  = fma2(A5, mvp[nt], plp[3]);
                plp[4]  = fma2(A3, mvp[nt], plp[4]);
                plp[5]  = fma2(A1, mvp[nt], plp[5]);
                plp[6]  = fma2(B1, mvp[nt], plp[6]);
                plp[7]  = fma2(B3, mvp[nt], plp[7]);
                plp[8]  = fma2(B5, mvp[nt], plp[8]);
                plp[9]  = fma2(B7, mvp[nt], plp[9]);
                plp[10] = fma2(B9, mvp[nt], plp[10]);
                // kernel 0 (sigma=1e-3, mu=1): rare guard, scalar
                const float d0 = s0 - 1.0f, d1f = s1 - 1.0f;
                if (fabsf(d0) < 0.0125f) {
                    const float u = d0 * 849.321802f;
                    pl0 = fmaf(mvd[nt * 2], ex2a(fmaxf(-u * u, -126.f)), pl0);
                }
                if (fabsf(d1f) < 0.0125f) {
                    const float u = d1f * 849.321802f;
                    pl0 = fmaf(mvd[nt * 2 + 1], ex2a(fmaxf(-u * u, -126.f)), pl0);
                }
            }
            float pl[N_K];
            pl[0] = pl0;
            #pragma unroll
            for (int k = 1; k < N_K; ++k) {
                float lo, hi; upk2(lo, hi, plp[k]);
                pl[k] = lo + hi;
            }
            #pragma unroll
            for (int k = 0; k < N_K; ++k) {
                float v = pl[k];
                v += __shfl_xor_sync(0xffffffffu, v, 1);
                v += __shfl_xor_sync(0xffffffffu, v, 2);
                if (c4 == 0) atomicAdd(&s_pool[row * N_K + k], v);
            }
        }
    }
    __syncthreads();

    // ---- publish doc-group partials; last CTA of this batch finalizes ----
    float* gp = g_pool + (size_t)(b * NDG + dg) * (L_Q * N_K);
    for (int i = tid; i < L_Q * N_K; i += NTHREADS) gp[i] = s_pool[i];
    __threadfence();
    __syncthreads();
    if (tid == 0) {
        unsigned int t = atomicAdd(&g_cnt[b], 1u);
        s_last = (t == NDG - 1);
    }
    __syncthreads();

    if (s_last) {
        __threadfence();
        const float* gb = g_pool + (size_t)b * NDG * L_Q * N_K;
        for (int i = tid; i < L_Q * N_K; i += NTHREADS) {
            float v = 0.f;
            #pragma unroll
            for (int c = 0; c < NDG; ++c) v += gb[c * (L_Q * N_K) + i];
            s_pool[i] = v;
        }
        __syncthreads();
        if (tid < L_Q) {
            const float mqv = mq[b * L_Q + tid] * 0.01f;
            float cm = 0.f;
            #pragma unroll
            for (int k = 0; k < N_K; ++k)
                cm = fmaf(logf(fmaxf(s_pool[tid * N_K + k], 1e-10f)) * mqv, w[k], cm);
            s_red[tid] = cm;
        }
        __syncthreads();
        if (tid == 0) {
            float s = bias[0];
            #pragma unroll
            for (int m = 0; m < L_Q; ++m) s += s_red[m];
            out[b] = tanhf(s);
            g_cnt[b] = 0;   // reset for next graph replay
        }
    }
}

extern "C" void kernel_launch(void* const* d_in, const int* in_sizes, int n_in,
                              void* d_out, int out_size) {
    const float* q    = (const float*)d_in[0];   // [B, Lq, E]
    const float* d    = (const float*)d_in[1];   // [B, Ld, E]
    const float* mq   = (const float*)d_in[2];   // [B, Lq]
    const float* md   = (const float*)d_in[3];   // [B, Ld]
    const float* w    = (const float*)d_in[4];   // [1, K]
    const float* bias = (const float*)d_in[5];   // [1]
    float* out = (float*)d_out;                  // [B, 1]

    cudaFuncSetAttribute(knrm_tf32, cudaFuncAttributeMaxDynamicSharedMemorySize, SMEM_BYTES);
    dim3 grid(NDG, B_SZ);
    knrm_tf32<<<grid, NTHREADS, SMEM_BYTES>>>(q, d, mq, md, w, bias, out);
}

// round 17
// speedup vs baseline: 1.0565x; 1.0064x over previous
#include <cuda_runtime.h>
#include <math.h>
#include <stdint.h>

#define B_SZ     128
#define L_Q      64
#define L_D      512
#define E_DIM    300
#define N_K      11
#define NDG      8          // doc-groups of 64 per batch; grid.x
#define DTG      64         // docs per CTA
#define NTHREADS 128
#define KC       32         // k per pipeline chunk
#define NCC      10         // chunks (10*32 = 320 >= 300)
#define NBUF     3          // pipeline depth
#define SW       36         // smem row stride (words) -> conflict-free LDSM

// smem word offsets
#define BUF_W     4608      // (64 A-rows + 64 B-rows) * 36
#define BOFF_B    2304      // 64*36
#define OFF_MASKD (NBUF * BUF_W)       // 64
#define OFF_SS    (OFF_MASKD + 64)     // 128 sumsq (q:0..63, d:64..127)
#define OFF_INV   (OFF_SS + 128)       // 128
#define OFF_RED   (OFF_INV + 128)      // 64
#define SMEM_WORDS (OFF_RED + 64)
#define SMEM_BYTES (SMEM_WORDS * 4)    // 56832 B -> 4 CTAs/SM

#define TF32_MASK 0xFFFFE000u   // bits mma.tf32 actually keeps (RZ truncation)

typedef unsigned long long u64;

__device__ float g_pool[B_SZ * L_Q * N_K];   // zero-init; last CTA re-zeros (replay safe)
__device__ unsigned int g_cnt[B_SZ];

__device__ __forceinline__ uint32_t smem_u32(const void* p) {
    uint32_t a;
    asm("{ .reg .u64 t; cvta.to.shared.u64 t, %1; cvt.u32.u64 %0, t; }" : "=r"(a) : "l"(p));
    return a;
}
__device__ __forceinline__ void mma_tf32(float* c, const uint32_t* a, uint32_t b0, uint32_t b1) {
    asm volatile("mma.sync.aligned.m16n8k8.row.col.f32.tf32.tf32.f32 "
        "{%0,%1,%2,%3},{%4,%5,%6,%7},{%8,%9},{%0,%1,%2,%3};"
        : "+f"(c[0]), "+f"(c[1]), "+f"(c[2]), "+f"(c[3])
        : "r"(a[0]), "r"(a[1]), "r"(a[2]), "r"(a[3]), "r"(b0), "r"(b1));
}
// 8x8 b16 ldmatrix == 8x4 tf32 tile; thread gets word at (lane/4, lane%4) == mma.tf32 frag
__device__ __forceinline__ void ldm_x4(uint32_t* r, uint32_t addr) {
    asm volatile("ldmatrix.sync.aligned.m8n8.x4.shared.b16 {%0,%1,%2,%3}, [%4];"
        : "=r"(r[0]), "=r"(r[1]), "=r"(r[2]), "=r"(r[3]) : "r"(addr));
}
__device__ __forceinline__ void cp16(uint32_t dst, const void* src, int sz) {
    asm volatile("cp.async.cg.shared.global [%0], [%1], 16, %2;"
        :: "r"(dst), "l"(src), "r"(sz) : "memory");
}
#define CP_COMMIT() asm volatile("cp.async.commit_group;" ::: "memory")
#define CP_WAIT0()  asm volatile("cp.async.wait_group 0;" ::: "memory")
#define CP_WAIT1()  asm volatile("cp.async.wait_group 1;" ::: "memory")

__device__ __forceinline__ float rcpa(float x) {
    float r; asm("rcp.approx.f32 %0,%1;" : "=f"(r) : "f"(x)); return r;
}
__device__ __forceinline__ float ex2a(float x) {   // MUFU 2^x
    float r; asm("ex2.approx.f32 %0,%1;" : "=f"(r) : "f"(x)); return r;
}
// packed f32x2 helpers (Blackwell dual-fp32 pipe)
__device__ __forceinline__ u64 pk2(float lo, float hi) {
    u64 r; asm("mov.b64 %0,{%1,%2};" : "=l"(r) : "f"(lo), "f"(hi)); return r;
}
__device__ __forceinline__ void upk2(float& lo, float& hi, u64 v) {
    asm("mov.b64 {%0,%1},%2;" : "=f"(lo), "=f"(hi) : "l"(v));
}
__device__ __forceinline__ u64 mul2(u64 a, u64 b) {
    u64 r; asm("mul.rn.f32x2 %0,%1,%2;" : "=l"(r) : "l"(a), "l"(b)); return r;
}
__device__ __forceinline__ u64 fma2(u64 a, u64 b, u64 c) {
    u64 r; asm("fma.rn.f32x2 %0,%1,%2,%3;" : "=l"(r) : "l"(a), "l"(b), "l"(c)); return r;
}

__global__ __launch_bounds__(NTHREADS, 4)
void knrm_tf32(const float* __restrict__ q,
               const float* __restrict__ d,
               const float* __restrict__ mq,
               const float* __restrict__ md,
               const float* __restrict__ w,
               const float* __restrict__ bias,
               float* __restrict__ out)
{
    extern __shared__ float smf[];
    __shared__ int s_last;

    float* s_maskd = smf + OFF_MASKD;
    float* s_ss    = smf + OFF_SS;
    float* s_inv   = smf + OFF_INV;
    float* s_red   = smf + OFF_RED;

    const uint32_t smb = smem_u32(smf);
    const int dg   = blockIdx.x;
    const int b    = blockIdx.y;
    const int tid  = threadIdx.x;
    const int lane = tid & 31;
    const int warp = tid >> 5;          // 0..3
    const int wm   = warp >> 1;         // 0..1 : q rows wm*32
    const int wn   = warp & 1;          // 0..1 : doc cols wn*32
    const int qrow = lane >> 2;
    const int c4   = lane & 3;

    const float* __restrict__ qb = q + (size_t)b * L_Q * E_DIM;
    const float* __restrict__ db = d + (size_t)b * L_D * E_DIM;

    for (int i = tid; i < DTG; i += NTHREADS)
        s_maskd[i] = md[b * L_D + dg * DTG + i];

    // ---- staging geometry: thread owns (row16-lane, 16B quad) ----
    const int r0   = tid >> 3;
    const int quad = tid & 7;
    const int koff = quad * 4;
    const float* baseA = qb + (size_t)r0 * E_DIM + koff;
    const float* baseB = db + (size_t)(dg * DTG + r0) * E_DIM + koff;
    const uint32_t dbaseA = smb + (r0 * SW + quad * 4) * 4;
    const uint32_t dbaseB = smb + (BOFF_B + r0 * SW + quad * 4) * 4;

    // ---- ldmatrix per-lane row addresses (buffer 0, s = 0) ----
    const int l15 = lane & 15;
    const int l7  = lane & 7;
    uint32_t aAddr[2], bAddr[2];
    #pragma unroll
    for (int mt = 0; mt < 2; ++mt)
        aAddr[mt] = smb + (((wm * 32 + mt * 16 + l15) * SW) + ((lane >> 4) << 2)) * 4;
    #pragma unroll
    for (int p = 0; p < 2; ++p)
        bAddr[p] = smb + ((BOFF_B + (wn * 32 + (p * 2 + ((lane >> 4) & 1)) * 8 + l7) * SW)
                          + (((lane >> 3) & 1) << 2)) * 4;

    float acc[2][4][4];
    #pragma unroll
    for (int mt = 0; mt < 2; ++mt)
        #pragma unroll
        for (int nt = 0; nt < 4; ++nt)
            #pragma unroll
            for (int c = 0; c < 4; ++c) acc[mt][nt][c] = 0.f;
    float ssA[4], ssB[4];
    #pragma unroll
    for (int i = 0; i < 4; ++i) { ssA[i] = 0.f; ssB[i] = 0.f; }

    #define ISSUE_CHUNK(cc) do {                                               \
        const int kb_ = (cc) * KC;                                             \
        const uint32_t bsel_ = ((cc) % NBUF) * (BUF_W * 4);                    \
        const int sz_ = (kb_ + koff < E_DIM) ? 16 : 0;                         \
        const float* pA_ = baseA + (sz_ ? kb_ : 0);                            \
        const float* pB_ = baseB + (sz_ ? kb_ : 0);                            \
        _Pragma("unroll")                                                      \
        for (int i_ = 0; i_ < 4; ++i_) {                                       \
            cp16(dbaseA + bsel_ + i_ * (16 * SW * 4), pA_ + i_ * (16 * E_DIM), sz_); \
            cp16(dbaseB + bsel_ + i_ * (16 * SW * 4), pB_ + i_ * (16 * E_DIM), sz_); \
        }                                                                      \
        CP_COMMIT();                                                           \
    } while (0)

    ISSUE_CHUNK(0);
    ISSUE_CHUNK(1);
    __syncthreads();   // mask loads visible (also spaces the pipeline start)

    #pragma unroll 1
    for (int cc = 0; cc < NCC; ++cc) {
        if (cc < NCC - 1) CP_WAIT1(); else CP_WAIT0();   // chunk cc resident
        __syncthreads();   // buffer cc visible to all; readers of buffer (cc-1) done
        if (cc + 2 < NCC) ISSUE_CHUNK(cc + 2);           // overwrites buffer (cc-1)%3

        const uint32_t bsel = (cc % NBUF) * (BUF_W * 4);
        #pragma unroll
        for (int s = 0; s < 4; ++s) {
            const uint32_t so = bsel + s * 32;
            uint32_t a[2][4], bb[2][4];
            ldm_x4(a[0], aAddr[0] + so);
            ldm_x4(a[1], aAddr[1] + so);
            ldm_x4(bb[0], bAddr[0] + so);   // {b0(nt0), b1(nt0), b0(nt1), b1(nt1)}
            ldm_x4(bb[1], bAddr[1] + so);   // {b0(nt2), b1(nt2), b0(nt3), b1(nt3)}

            // norms on the TRUNCATED words -> tf32 bias cancels in the cosine
            if (wn == 0) {
                #pragma unroll
                for (int mt = 0; mt < 2; ++mt) {
                    float a0 = __uint_as_float(a[mt][0] & TF32_MASK);
                    float a1 = __uint_as_float(a[mt][1] & TF32_MASK);
                    float a2 = __uint_as_float(a[mt][2] & TF32_MASK);
                    float a3 = __uint_as_float(a[mt][3] & TF32_MASK);
                    ssA[mt * 2 + 0] = fmaf(a0, a0, fmaf(a2, a2, ssA[mt * 2 + 0]));
                    ssA[mt * 2 + 1] = fmaf(a1, a1, fmaf(a3, a3, ssA[mt * 2 + 1]));
                }
            }
            if (wm == 0) {
                #pragma unroll
                for (int p = 0; p < 2; ++p) {
                    #pragma unroll
                    for (int j = 0; j < 2; ++j) {
                        float b0 = __uint_as_float(bb[p][j * 2 + 0] & TF32_MASK);
                        float b1 = __uint_as_float(bb[p][j * 2 + 1] & TF32_MASK);
                        ssB[p * 2 + j] = fmaf(b0, b0, fmaf(b1, b1, ssB[p * 2 + j]));
                    }
                }
            }
            #pragma unroll
            for (int mt = 0; mt < 2; ++mt)
                #pragma unroll
                for (int nt = 0; nt < 4; ++nt)
                    mma_tf32(acc[mt][nt], a[mt], bb[nt >> 1][(nt & 1) * 2],
                             bb[nt >> 1][(nt & 1) * 2 + 1]);
        }
    }

    // ---- norms ----
    #pragma unroll
    for (int i = 0; i < 4; ++i) {
        ssA[i] += __shfl_xor_sync(0xffffffffu, ssA[i], 1);
        ssA[i] += __shfl_xor_sync(0xffffffffu, ssA[i], 2);
        ssB[i] += __shfl_xor_sync(0xffffffffu, ssB[i], 1);
        ssB[i] += __shfl_xor_sync(0xffffffffu, ssB[i], 2);
    }
    if (c4 == 0) {
        if (wn == 0) {
            #pragma unroll
            for (int mt = 0; mt < 2; ++mt)
                #pragma unroll
                for (int rh = 0; rh < 2; ++rh)
                    s_ss[wm * 32 + mt * 16 + rh * 8 + qrow] = ssA[mt * 2 + rh];
        }
        if (wm == 0) {
            #pragma unroll
            for (int nt = 0; nt < 4; ++nt)
                s_ss[64 + wn * 32 + nt * 8 + qrow] = ssB[nt];
        }
    }
    __syncthreads();
    s_inv[tid] = 1.0f / fmaxf(sqrtf(s_ss[tid]), 1e-12f);
    __syncthreads();

    // ---- pooling from fragments: MUFU exps + packed f32x2 kernel chain ----
    const u64 K1 = pk2(0.60653066f,  0.60653066f);
    const u64 K3 = pk2(0.018315639f, 0.018315639f);
    const u64 K5 = pk2(3.3546263e-4f, 3.3546263e-4f);
    const u64 K7 = pk2(6.1442124e-6f, 6.1442124e-6f);
    const u64 K9 = pk2(1.1253517e-7f, 1.1253517e-7f);

    float* gpb = g_pool + (size_t)b * (L_Q * N_K);

    float ivd[8], mvd[8];
    u64 mvp[4];
    #pragma unroll
    for (int nt = 0; nt < 4; ++nt) {
        #pragma unroll
        for (int cm = 0; cm < 2; ++cm) {
            const int nl = wn * 32 + nt * 8 + c4 * 2 + cm;
            ivd[nt * 2 + cm] = s_inv[64 + nl];
            mvd[nt * 2 + cm] = s_maskd[nl];
        }
        mvp[nt] = pk2(mvd[nt * 2], mvd[nt * 2 + 1]);
    }
    #pragma unroll
    for (int mt = 0; mt < 2; ++mt) {
        #pragma unroll
        for (int rh = 0; rh < 2; ++rh) {
            const int row = wm * 32 + mt * 16 + qrow + rh * 8;
            const float iq = s_inv[row];
            u64 plp[N_K];
            #pragma unroll
            for (int k = 1; k < N_K; ++k) plp[k] = 0ULL;
            float pl0 = 0.f;
            #pragma unroll
            for (int nt = 0; nt < 4; ++nt) {
                const float s0 = acc[mt][nt][rh * 2 + 0] * iq * ivd[nt * 2 + 0];
                const float s1 = acc[mt][nt][rh * 2 + 1] * iq * ivd[nt * 2 + 1];
                const float e0 = ex2a(fmaxf(s0 * s0 * -72.134752f, -126.f));
                const float e1 = ex2a(fmaxf(s1 * s1 * -72.134752f, -126.f));
                const float t0 = ex2a(s0 * 14.4269504f);
                const float t1 = ex2a(s1 * 14.4269504f);
                const u64 bp = pk2(e0, e1);
                const u64 tp = pk2(t0, t1);
                const u64 rp = pk2(rcpa(t0), rcpa(t1));
                const u64 t2 = mul2(tp, tp), r2 = mul2(rp, rp);
                const u64 A1 = mul2(mul2(bp, tp), K1);
                const u64 A3 = mul2(mul2(A1, t2), K3);
                const u64 A5 = mul2(mul2(A3, t2), K5);
                const u64 A7 = mul2(mul2(A5, t2), K7);
                const u64 A9 = mul2(mul2(A7, t2), K9);
                const u64 B1 = mul2(mul2(bp, rp), K1);
                const u64 B3 = mul2(mul2(B1, r2), K3);
                const u64 B5 = mul2(mul2(B3, r2), K5);
                const u64 B7 = mul2(mul2(B5, r2), K7);
                const u64 B9 = mul2(mul2(B7, r2), K9);
                plp[1]  = fma2(A9, mvp[nt], plp[1]);
                plp[2]  = fma2(A7, mvp[nt], plp[2]);
                plp[3]  = fma2(A5, mvp[nt], plp[3]);
                plp[4]  = fma2(A3, mvp[nt], plp[4]);
                plp[5]  = fma2(A1, mvp[nt], plp[5]);
                plp[6]  = fma2(B1, mvp[nt], plp[6]);
                plp[7]  = fma2(B3, mvp[nt], plp[7]);
                plp[8]  = fma2(B5, mvp[nt], plp[8]);
                plp[9]  = fma2(B7, mvp[nt], plp[9]);
                plp[10] = fma2(B9, mvp[nt], plp[10]);
                // kernel 0 (sigma=1e-3, mu=1): rare guard, scalar
                const float d0 = s0 - 1.0f, d1f = s1 - 1.0f;
                if (fabsf(d0) < 0.0125f) {
                    const float u = d0 * 849.321802f;
                    pl0 = fmaf(mvd[nt * 2], ex2a(fmaxf(-u * u, -126.f)), pl0);
                }
                if (fabsf(d1f) < 0.0125f) {
                    const float u = d1f * 849.321802f;
                    pl0 = fmaf(mvd[nt * 2 + 1], ex2a(fmaxf(-u * u, -126.f)), pl0);
                }
            }
            float pl[N_K];
            pl[0] = pl0;
            #pragma unroll
            for (int k = 1; k < N_K; ++k) {
                float lo, hi; upk2(lo, hi, plp[k]);
                pl[k] = lo + hi;
            }
            // quad reduce, then accumulate straight into the per-batch global pool
            #pragma unroll
            for (int k = 0; k < N_K; ++k) {
                float v = pl[k];
                v += __shfl_xor_sync(0xffffffffu, v, 1);
                v += __shfl_xor_sync(0xffffffffu, v, 2);
                if (c4 == 0) atomicAdd(&gpb[row * N_K + k], v);
            }
        }
    }

    // ---- last CTA of this batch finalizes ----
    __threadfence();
    __syncthreads();
    if (tid == 0) {
        unsigned int t = atomicAdd(&g_cnt[b], 1u);
        s_last = (t == NDG - 1);
    }
    __syncthreads();

    if (s_last) {
        __threadfence();
        if (tid < L_Q) {
            const float mqv = mq[b * L_Q + tid] * 0.01f;
            float cm = 0.f;
            #pragma unroll
            for (int k = 0; k < N_K; ++k)
                cm = fmaf(logf(fmaxf(gpb[tid * N_K + k], 1e-10f)) * mqv, w[k], cm);
            s_red[tid] = cm;
        }
        __syncthreads();
        if (tid == 0) {
            float s = bias[0];
            #pragma unroll
            for (int m = 0; m < L_Q; ++m) s += s_red[m];
            out[b] = tanhf(s);
            g_cnt[b] = 0;   // reset for next graph replay
        }
        // re-zero the pool region for the next replay
        for (int i = tid; i < L_Q * N_K; i += NTHREADS) gpb[i] = 0.f;
    }
}

extern "C" void kernel_launch(void* const* d_in, const int* in_sizes, int n_in,
                              void* d_out, int out_size) {
    const float* q    = (const float*)d_in[0];   // [B, Lq, E]
    const float* d    = (const float*)d_in[1];   // [B, Ld, E]
    const float* mq   = (const float*)d_in[2];   // [B, Lq]
    const float* md   = (const float*)d_in[3];   // [B, Ld]
    const float* w    = (const float*)d_in[4];   // [1, K]
    const float* bias = (const float*)d_in[5];   // [1]
    float* out = (float*)d_out;                  // [B, 1]

    cudaFuncSetAttribute(knrm_tf32, cudaFuncAttributeMaxDynamicSharedMemorySize, SMEM_BYTES);
    dim3 grid(NDG, B_SZ);
    knrm_tf32<<<grid, NTHREADS, SMEM_BYTES>>>(q, d, mq, md, w, bias, out);
}